// round 8
// baseline (speedup 1.0000x reference)
#include <cuda_runtime.h>
#include <cuda_fp16.h>
#include <cstdint>

// ---------------------------------------------------------------------------
// LinearPatchMerger (GB300, family-safe):
//   prep_w:  g_Wh[1024][4096] = fp16( column-permuted W )
//   gemm  :  out[32768,1024] = unfold(X)@g_Wh^T, mma.m16n8k16.f16 (f32 accum)
//            A-side: direct f32 LDG from X + in-register f16 convert (fused).
// ---------------------------------------------------------------------------

constexpr int K_TOT = 4096;
constexpr int N_TOT = 1024;

constexpr int KC = 64;               // K elems per stage (128 B f16 rows)
constexpr int NCHUNK = K_TOT / KC;   // 64
constexpr int NSTAGE = 3;
constexpr int THREADS = 128;         // 4 warps, 2x2 of 64x64 warp tiles

constexpr int A_BYTES = 128 * KC * 2;        // 16 KB (f16)
constexpr int B_BYTES = 128 * KC * 2;        // 16 KB (f16)
constexpr int STAGE   = A_BYTES + B_BYTES;   // 32 KB
constexpr int SMEM_BYTES = NSTAGE * STAGE;   // 96 KB

__device__ __half g_Wh[(size_t)N_TOT * K_TOT];  // 8 MB permuted fp16 W

#define DEV __device__ __forceinline__

DEV uint32_t smem_u32(const void* p) {
    uint32_t a;
    asm("{ .reg .u64 t; cvta.to.shared.u64 t, %1; cvt.u32.u64 %0, t; }"
        : "=r"(a) : "l"(p));
    return a;
}
DEV void cp16(uint32_t dst, const void* src) {
    asm volatile("cp.async.ca.shared.global [%0], [%1], 16;"
                 :: "r"(dst), "l"(src) : "memory");
}
DEV void cp_commit() { asm volatile("cp.async.commit_group;" ::: "memory"); }
template <int N> DEV void cp_wait() {
    asm volatile("cp.async.wait_group %0;" :: "n"(N) : "memory");
}
DEV void sts64(uint32_t a, uint32_t x, uint32_t y) {
    asm volatile("st.shared.v2.b32 [%0], {%1,%2};" :: "r"(a), "r"(x), "r"(y)
                 : "memory");
}
DEV void ldmx4(uint32_t* r, uint32_t a) {
    asm volatile("ldmatrix.sync.aligned.m8n8.x4.shared.b16 {%0,%1,%2,%3}, [%4];"
                 : "=r"(r[0]), "=r"(r[1]), "=r"(r[2]), "=r"(r[3]) : "r"(a));
}
DEV void mma_f16(float* d, const uint32_t* a, uint32_t b0, uint32_t b1) {
    asm volatile(
        "mma.sync.aligned.m16n8k16.row.col.f32.f16.f16.f32 "
        "{%0,%1,%2,%3}, {%4,%5,%6,%7}, {%8,%9}, {%0,%1,%2,%3};"
        : "+f"(d[0]), "+f"(d[1]), "+f"(d[2]), "+f"(d[3])
        : "r"(a[0]), "r"(a[1]), "r"(a[2]), "r"(a[3]), "r"(b0), "r"(b1));
}
DEV uint32_t h2u(__half2 h) { return *(uint32_t*)&h; }

// ---------------------------------------------------------------------------
// prep W (input-indexed, fully coalesced both sides):
//   thread o: v = W[dout][4d..4d+3];  g_Wh[dout][q*1024+d] = fp16(v[q])
// ---------------------------------------------------------------------------
__global__ void prep_w_kernel(const float* __restrict__ W) {
    int o = blockIdx.x * blockDim.x + threadIdx.x;   // 0 .. 1M-1
    if (o >= N_TOT * K_TOT / 4) return;
    int dout = o >> 10;
    int d    = o & 1023;
    float4 v = ((const float4*)W)[o];
    __half* base = g_Wh + ((size_t)dout << 12) + d;
    base[0]    = __float2half_rn(v.x);
    base[1024] = __float2half_rn(v.y);
    base[2048] = __float2half_rn(v.z);
    base[3072] = __float2half_rn(v.w);
}

// ---------------------------------------------------------------------------
// GEMM: grid (8 n-tiles, 256 m-tiles), 128 threads, warp tile 64x64.
// smem rows = 64 halves (128 B); 16B-chunk swizzle  cc ^ (row & 7).
// A producer: LDG.128 f32 (1 iter lookahead) -> cvt f16x2 -> STS.64.
// B producer: cp.async from g_Wh.
// ---------------------------------------------------------------------------
__global__ void __launch_bounds__(THREADS, 2)
merger_gemm_kernel(const float* __restrict__ X, float* __restrict__ out) {
    extern __shared__ __align__(1024) char sm[];
    const uint32_t sbase = smem_u32(sm);

    const int tid = threadIdx.x;
    const int wid = tid >> 5;
    const int lid = tid & 31;
    const int bx  = blockIdx.x;     // n-tile 0..7
    const int mt  = blockIdx.y;     // m-tile 0..255

    const int warp_m = wid & 1;
    const int warp_n = wid >> 1;
    const int g   = lid >> 2;
    const int tig = lid & 3;

    // ---- A producer slots: 16 float4 / thread / stage ----
    // slot f = tid + k*128 : row r = f>>4 (0..127), c = f&15 (float4 in 64-f32 row)
    int rbA[16];           // source patch-row base (sans quadrant)
    uint32_t stsA[16];     // swizzled smem byte offset (8B granule)
    int ldc4[16];          // float offset within row
    #pragma unroll
    for (int k = 0; k < 16; k++) {
        int f = tid + (k << 7);
        int r = f >> 4;
        int c = f & 15;
        int i = ((mt & 31) << 1) + (r >> 6);
        int j = r & 63;
        rbA[k]  = (i << 8) + (j << 1);
        ldc4[k] = c << 2;
        int cc  = c >> 1;
        stsA[k] = (uint32_t)(r * 128 + ((cc ^ (r & 7)) << 4) + ((c & 1) << 3));
    }
    // ---- B producer slots: 8 cp16 / thread / stage ----
    uint32_t stsB[8];
    const __half* srcB[8];
    #pragma unroll
    for (int k = 0; k < 8; k++) {
        int f = tid + (k << 7);
        int r = f >> 3;
        int c = f & 7;
        stsB[k] = (uint32_t)(r * 128 + ((c ^ (r & 7)) << 4));
        srcB[k] = g_Wh + ((size_t)(bx * 128 + r) << 12) + (c << 3);
    }

    const float* Xi = X + (size_t)(mt >> 5) * (16384u * 1024u);

    // ---- consumer ldmatrix geometry ----
    const int rA  = (lid & 15);
    const int cbA = lid >> 4;
    const int rB  = ((lid >> 4) << 3) + (lid & 7);
    const int cbB = (lid >> 3) & 1;

    float acc[4][8][4];
    #pragma unroll
    for (int mi = 0; mi < 4; mi++)
        #pragma unroll
        for (int ni = 0; ni < 8; ni++)
            #pragma unroll
            for (int r = 0; r < 4; r++) acc[mi][ni][r] = 0.0f;

    float4 pre[16];        // A prefetch buffer (1-iteration lookahead)

    auto ldgA = [&](int kc) {
        const int q    = kc >> 4;
        const int d0   = (kc & 15) << 6;
        const int qrow = ((q >> 1) << 7) + (q & 1);
        #pragma unroll
        for (int k = 0; k < 16; k++)
            pre[k] = *(const float4*)(Xi + ((size_t)(rbA[k] + qrow) << 10)
                                      + d0 + ldc4[k]);
    };
    auto stsA_stage = [&](int st) {
        const uint32_t aS = sbase + st * STAGE;
        #pragma unroll
        for (int k = 0; k < 16; k++) {
            uint32_t u0 = h2u(__floats2half2_rn(pre[k].x, pre[k].y));
            uint32_t u1 = h2u(__floats2half2_rn(pre[k].z, pre[k].w));
            sts64(aS + stsA[k], u0, u1);
        }
    };
    auto cpB_stage = [&](int st, int kc) {
        const uint32_t bS = sbase + st * STAGE + A_BYTES;
        #pragma unroll
        for (int k = 0; k < 8; k++) cp16(bS + stsB[k], srcB[k] + kc * KC);
    };

    // ---- prologue ----
    ldgA(0);
    #pragma unroll
    for (int s = 0; s < NSTAGE - 1; s++) {
        stsA_stage(s);
        cpB_stage(s, s);
        cp_commit();
        ldgA(s + 1);
    }
    int kc_load = NSTAGE - 1;

    // ---- mainloop ----
    for (int kc = 0; kc < NCHUNK; kc++) {
        cp_wait<NSTAGE - 2>();
        __syncthreads();

        if (kc_load < NCHUNK) {
            const int st = kc_load % NSTAGE;
            stsA_stage(st);
            cpB_stage(st, kc_load);
            const int nxt = kc_load + 1;
            ldgA(nxt < NCHUNK ? nxt : NCHUNK - 1);
            kc_load++;
        }
        cp_commit();

        const uint32_t aS = sbase + (kc % NSTAGE) * STAGE;
        const uint32_t bS = aS + A_BYTES;

        #pragma unroll
        for (int s = 0; s < 4; s++) {
            uint32_t afr[4][4];
            #pragma unroll
            for (int mi = 0; mi < 4; mi++) {
                int row = warp_m * 64 + mi * 16 + rA;
                int ch  = (2 * s + cbA) ^ (row & 7);
                ldmx4(afr[mi], aS + row * 128 + (ch << 4));
            }
            uint32_t bfr[4][4];
            #pragma unroll
            for (int nj = 0; nj < 4; nj++) {
                int row = warp_n * 64 + nj * 16 + rB;
                int ch  = (2 * s + cbB) ^ (row & 7);
                ldmx4(bfr[nj], bS + row * 128 + (ch << 4));
            }
            #pragma unroll
            for (int mi = 0; mi < 4; mi++)
                #pragma unroll
                for (int ni = 0; ni < 8; ni++)
                    mma_f16(acc[mi][ni], afr[mi],
                            bfr[ni >> 1][(ni & 1) * 2],
                            bfr[ni >> 1][(ni & 1) * 2 + 1]);
        }
    }

    // ---- epilogue ----
    const int row0 = mt * 128 + warp_m * 64 + g;
    const int col0 = bx * 128 + warp_n * 64 + tig * 2;
    #pragma unroll
    for (int mi = 0; mi < 4; mi++) {
        #pragma unroll
        for (int ni = 0; ni < 8; ni++) {
            float* p0 = out + (size_t)(row0 + mi * 16) * N_TOT + col0 + ni * 8;
            *(float2*)p0               = make_float2(acc[mi][ni][0], acc[mi][ni][1]);
            *(float2*)(p0 + 8 * N_TOT) = make_float2(acc[mi][ni][2], acc[mi][ni][3]);
        }
    }
}

// ---------------------------------------------------------------------------
extern "C" void kernel_launch(void* const* d_in, const int* in_sizes, int n_in,
                              void* d_out, int out_size) {
    (void)in_sizes; (void)n_in; (void)out_size;
    const float* X = (const float*)d_in[0];   // (1,131072,1024) f32
    const float* W = (const float*)d_in[2];   // (1024,4096) f32
    float* out = (float*)d_out;               // (1,32768,1024) f32

    cudaFuncSetAttribute(merger_gemm_kernel,
                         cudaFuncAttributeMaxDynamicSharedMemorySize, SMEM_BYTES);

    prep_w_kernel<<<(N_TOT * K_TOT / 4 + 255) / 256, 256>>>(W);
    merger_gemm_kernel<<<dim3(8, 256, 1), THREADS, SMEM_BYTES>>>(X, out);
}